// round 13
// baseline (speedup 1.0000x reference)
#include <cuda_runtime.h>
#include <cstdint>

#define H_ 512
#define W_ 512
#define G_ 83
#define KK 12
#define NB 8
#define NV (G_ * G_)                 // 6889 vertices
#define NF (2 * (G_ - 1) * (G_ - 1)) // 13448 faces
#define HW (H_ * W_)
#define NTRI (NB * NF)               // 107584 (even)

// 16 MB z-buffer scratch, re-initialized each replay by prep_kernel.
__device__ unsigned long long g_zbuf[NB * HW];
// Per-(batch,triangle) setup: 3 x float4 per tri.
//  s0 = (x0, y0, x1, y1)
//  s1 = (x2, y2, z0, z1)
//  s2 = (z2, invA, bits(xlo|ylo<<9|bw<<18), bits(magic|cnt<<17))
__device__ float4 g_setup[NTRI * 3];
// Faces padded to int4 for single 128-bit loads (shade uv lookup).
__device__ int4 g_faces4[NF];

// Strict IEEE, non-fused edge function: (a-b)*(c-d) - (e-f)*(g-h)
__device__ __forceinline__ float edgefn(float a, float b, float c, float d,
                                        float e, float f, float g, float h) {
    float t1 = __fmul_rn(__fsub_rn(a, b), __fsub_rn(c, d));
    float t2 = __fmul_rn(__fsub_rn(e, f), __fsub_rn(g, h));
    return __fsub_rn(t1, t2);
}

// Combined prep: 32B-store z-buffer fill + per-triangle full setup + face pad.
// Tri setup reads verts/faces directly (no intra-kernel dependencies).
__global__ void prep_kernel(const float* __restrict__ verts,
                            const int* __restrict__ faces) {
    int i = blockIdx.x * blockDim.x + threadIdx.x;
    if (i < (NB * HW) / 4) {
        ulonglong2 s = make_ulonglong2(0xFFFFFFFFFFFFFFFFull,
                                       0xFFFFFFFFFFFFFFFFull);
        ulonglong2* p = reinterpret_cast<ulonglong2*>(g_zbuf) + i * 2;
        p[0] = s;
        p[1] = s;
    }
    if (i < NF) {
        g_faces4[i] = make_int4(faces[3 * i + 0], faces[3 * i + 1],
                                faces[3 * i + 2], 0);
    }
    if (i < NTRI) {
        int n = i / NF;
        int f = i - n * NF;
        int i0 = faces[3 * f + 0];
        int i1 = faces[3 * f + 1];
        int i2 = faces[3 * f + 2];
        const float* vb = verts + (size_t)n * NV * 3;
        float z0 = vb[3 * i0 + 2], z1 = vb[3 * i1 + 2], z2 = vb[3 * i2 + 2];
        // Bit-identical projection: p = v * (1/z), correctly-rounded recip.
        float r0 = __fdiv_rn(1.0f, z0), r1 = __fdiv_rn(1.0f, z1), r2 = __fdiv_rn(1.0f, z2);
        float x0 = __fmul_rn(vb[3 * i0 + 0], r0), y0 = __fmul_rn(vb[3 * i0 + 1], r0);
        float x1 = __fmul_rn(vb[3 * i1 + 0], r1), y1 = __fmul_rn(vb[3 * i1 + 1], r1);
        float x2 = __fmul_rn(vb[3 * i2 + 0], r2), y2 = __fmul_rn(vb[3 * i2 + 1], r2);

        float area = edgefn(x1, x0, y2, y0, y1, y0, x2, x0);
        bool ok = (z0 > 0.f) && (z1 > 0.f) && (z2 > 0.f) && (fabsf(area) > 1e-9f);
        float invA = __fdiv_rn(1.0f, area);

        float xmn = fminf(x0, fminf(x1, x2));
        float xmx = fmaxf(x0, fmaxf(x1, x2));
        float ymn = fminf(y0, fminf(y1, y2));
        float ymx = fmaxf(y0, fmaxf(y1, y2));
        int fxmn = (int)floorf(xmn);
        int fymn = (int)floorf(ymn);
        int bcx = min(max(fxmn, 0), W_ - KK);
        int bcy = min(max(fymn, 0), H_ - KK);
        // Compact candidate rect (proven exact: excluded pixels are >=1px
        // outside the vertex extent where a barycentric is <= -1/12 exactly).
        int xlo = max(bcx, fxmn);
        int xhi = min(bcx + KK - 1, (int)ceilf(xmx));
        int ylo = max(bcy, fymn);
        int yhi = min(bcy + KK - 1, (int)ceilf(ymx));
        int bw = xhi - xlo + 1;
        int bh = yhi - ylo + 1;
        int cnt = (ok && bw > 0 && bh > 0) ? bw * bh : 0;
        int bwc = max(bw, 1);
        unsigned magic = (65536u + (unsigned)bwc - 1) / (unsigned)bwc;

        int pk = xlo | (ylo << 9) | (min(max(bw, 0), 15) << 18);
        unsigned pk2 = magic | ((unsigned)cnt << 17);

        g_setup[3 * i + 0] = make_float4(x0, y0, x1, y1);
        g_setup[3 * i + 1] = make_float4(x2, y2, z0, z1);
        g_setup[3 * i + 2] = make_float4(z2, invA,
                                         __int_as_float(pk),
                                         __uint_as_float(pk2));
    }
}

// TWO triangles per warp: lanes 0-15 -> tri 2*gw, lanes 16-31 -> tri 2*gw+1.
// All per-triangle setup is preloaded from g_setup (3 x LDG.128).
__global__ void raster_kernel() {
    int gw = (blockIdx.x * blockDim.x + threadIdx.x) >> 5;
    int lane = threadIdx.x & 31;
    if (gw >= NTRI / 2) return;
    int sub = lane & 15;
    int tri = gw * 2 + (lane >> 4);
    int n = tri / NF;
    int f = tri - n * NF;

    float4 s0 = g_setup[3 * tri + 0];
    float4 s1 = g_setup[3 * tri + 1];
    float4 s2 = g_setup[3 * tri + 2];
    float x0 = s0.x, y0 = s0.y, x1 = s0.z, y1 = s0.w;
    float x2 = s1.x, y2 = s1.y, z0 = s1.z, z1 = s1.w;
    float z2 = s2.x, invA = s2.y;
    int pk = __float_as_int(s2.z);
    unsigned pk2 = __float_as_uint(s2.w);
    int xlo = pk & 511;
    int ylo = (pk >> 9) & 511;
    int bw = (pk >> 18) & 15;
    unsigned magic = pk2 & 0x1FFFFu;
    int cnt = (int)(pk2 >> 17);

    unsigned long long* zb = g_zbuf + (size_t)n * HW;

    for (int t = sub; t < cnt; t += 16) {
        int oy = (int)(((unsigned)t * magic) >> 16);   // exact t/bw
        int ox = t - oy * bw;
        int px = xlo + ox;
        int py = ylo + oy;
        float pxf = (float)px, pyf = (float)py;
        float w0 = __fmul_rn(edgefn(x2, x1, pyf, y1, y2, y1, pxf, x1), invA);
        float w1 = __fmul_rn(edgefn(x0, x2, pyf, y2, y0, y2, pxf, x2), invA);
        float w2 = __fsub_rn(__fsub_rn(1.0f, w0), w1);
        if (w0 >= 0.f && w1 >= 0.f && w2 >= 0.f) {
            float depth = __fadd_rn(
                __fadd_rn(__fmul_rn(w0, z0), __fmul_rn(w1, z1)),
                __fmul_rn(w2, z2));
            // Same-pixel ties only arise between DIFFERENT triangles, so
            // packing f preserves the reference's (depth, m) tie-break.
            unsigned long long packed =
                ((unsigned long long)__float_as_uint(depth) << 32) |
                (unsigned int)f;
            atomicMin(zb + py * W_ + px, packed);
        }
    }
}

// One thread per (batch, pixel): decode winner face, load its precomputed
// setup (incl. invA), recompute barycentrics with identical arithmetic,
// interpolate uv, apply epilogue.
__global__ void shade_kernel(const float* __restrict__ vals,
                             float* __restrict__ out) {
    int gid = blockIdx.x * blockDim.x + threadIdx.x;
    if (gid >= NB * HW) return;
    int n = gid / HW;
    int pix = gid - n * HW;

    unsigned long long zv = g_zbuf[gid];
    float u = 0.f, v = 0.f;
    if (zv != 0xFFFFFFFFFFFFFFFFull) {
        int f = (int)(unsigned int)(zv & 0xFFFFFFFFu);
        int tri = n * NF + f;
        float4 s0 = g_setup[3 * tri + 0];
        float4 s1 = g_setup[3 * tri + 1];
        float4 s2 = g_setup[3 * tri + 2];
        float x0 = s0.x, y0 = s0.y, x1 = s0.z, y1 = s0.w;
        float x2 = s1.x, y2 = s1.y;
        float invA = s2.y;
        int px = pix & (W_ - 1);
        int py = pix >> 9;
        float pxf = (float)px, pyf = (float)py;
        float w0 = __fmul_rn(edgefn(x2, x1, pyf, y1, y2, y1, pxf, x1), invA);
        float w1 = __fmul_rn(edgefn(x0, x2, pyf, y2, y0, y2, pxf, x2), invA);
        float w2 = __fsub_rn(__fsub_rn(1.0f, w0), w1);
        int4 fc = g_faces4[f];
        const float2* vl = reinterpret_cast<const float2*>(vals);
        float2 va = vl[fc.x];
        float2 vbv = vl[fc.y];
        float2 vc = vl[fc.z];
        u = __fadd_rn(
            __fadd_rn(__fmul_rn(w0, va.x), __fmul_rn(w1, vbv.x)),
            __fmul_rn(w2, vc.x));
        v = __fadd_rn(
            __fadd_rn(__fmul_rn(w0, va.y), __fmul_rn(w1, vbv.y)),
            __fmul_rn(w2, vc.y));
    }
    float mask = (u > 0.f || v > 0.f) ? 1.f : 0.f;
    float ou, ov;
    if (mask > 0.f) {
        ou = __fsub_rn(__fmul_rn(2.f, u), 1.f);
        ov = __fsub_rn(__fmul_rn(2.f, v), 1.f);
    } else {
        ou = -10.f;
        ov = -10.f;
    }
    out[((size_t)n * 2 + 0) * HW + pix] = ou;
    out[((size_t)n * 2 + 1) * HW + pix] = ov;
    out[(size_t)NB * 2 * HW + (size_t)n * HW + pix] = mask;
}

extern "C" void kernel_launch(void* const* d_in, const int* in_sizes, int n_in,
                              void* d_out, int out_size) {
    const float* verts = (const float*)d_in[0];
    const int* faces = (const int*)d_in[1];
    const float* vals = (const float*)d_in[2];
    float* out = (float*)d_out;

    (void)in_sizes; (void)n_in; (void)out_size;

    int prepThreads = (NB * HW) / 4;                 // 524288 covers everything
    int prepBlocks = (prepThreads + 255) / 256;
    prep_kernel<<<prepBlocks, 256>>>(verts, faces);

    int nwarps = NTRI / 2;                 // 53792 warps, 2 tri each
    int rasterBlocks = (nwarps * 32 + 255) / 256;
    raster_kernel<<<rasterBlocks, 256>>>();

    int shadeBlocks = (NB * HW + 255) / 256;
    shade_kernel<<<shadeBlocks, 256>>>(vals, out);
}

// round 14
// speedup vs baseline: 1.1632x; 1.1632x over previous
#include <cuda_runtime.h>
#include <cstdint>

#define H_ 512
#define W_ 512
#define G_ 83
#define KK 12
#define NB 8
#define NV (G_ * G_)                 // 6889 vertices
#define NF (2 * (G_ - 1) * (G_ - 1)) // 13448 faces
#define HW (H_ * W_)
#define NBNV (NB * NV)
#define NTRI (NB * NF)               // 107584 (even)

// 16 MB z-buffer scratch, re-initialized each replay by prep_kernel.
__device__ unsigned long long g_zbuf[NB * HW];
// Precomputed projected vertices per (batch, vertex): (x, y, z, 0).
__device__ float4 g_pv[NBNV];
// Faces padded to int4 for single 128-bit loads.
__device__ int4 g_faces4[NF];

// Strict IEEE, non-fused edge function: (a-b)*(c-d) - (e-f)*(g-h)
__device__ __forceinline__ float edgefn(float a, float b, float c, float d,
                                        float e, float f, float g, float h) {
    float t1 = __fmul_rn(__fsub_rn(a, b), __fsub_rn(c, d));
    float t2 = __fmul_rn(__fsub_rn(e, f), __fsub_rn(g, h));
    return __fsub_rn(t1, t2);
}

// Combined prep (R12-proven): 16B-store fill + vertex projection + face pad.
__global__ void prep_kernel(const float* __restrict__ verts,
                            const int* __restrict__ faces) {
    int i = blockIdx.x * blockDim.x + threadIdx.x;
    if (i < (NB * HW) / 2) {
        ulonglong2 s = make_ulonglong2(0xFFFFFFFFFFFFFFFFull,
                                       0xFFFFFFFFFFFFFFFFull);
        reinterpret_cast<ulonglong2*>(g_zbuf)[i] = s;
    }
    if (i < NBNV) {
        float vx = verts[3 * i + 0];
        float vy = verts[3 * i + 1];
        float vz = verts[3 * i + 2];
        float r = __fdiv_rn(1.0f, vz);   // bit-identical hoisted projection
        g_pv[i] = make_float4(__fmul_rn(vx, r), __fmul_rn(vy, r), vz, 0.0f);
    }
    if (i < NF) {
        g_faces4[i] = make_int4(faces[3 * i + 0], faces[3 * i + 1],
                                faces[3 * i + 2], 0);
    }
}

// TWO triangles per warp: lanes 0-15 -> tri 2*gw, lanes 16-31 -> tri 2*gw+1.
// Each 16-lane half iterates a COMPACT bbox-clipped candidate set (proven
// exact: excluded pixels are >=1px outside the vertex extent where some
// barycentric is <= -1/12 exactly; fp noise cannot flip the w>=0 test).
__global__ void raster_kernel() {
    int gw = (blockIdx.x * blockDim.x + threadIdx.x) >> 5;
    int lane = threadIdx.x & 31;
    if (gw >= NTRI / 2) return;
    int sub = lane & 15;
    int tri = gw * 2 + (lane >> 4);
    int n = tri / NF;
    int f = tri - n * NF;

    int4 fc = g_faces4[f];
    const float4* pv = g_pv + n * NV;
    float4 p0 = pv[fc.x];
    float4 p1 = pv[fc.y];
    float4 p2 = pv[fc.z];
    float x0 = p0.x, y0 = p0.y, z0 = p0.z;
    float x1 = p1.x, y1 = p1.y, z1 = p1.z;
    float x2 = p2.x, y2 = p2.y, z2 = p2.z;

    float area = edgefn(x1, x0, y2, y0, y1, y0, x2, x0);
    bool ok = (z0 > 0.f) && (z1 > 0.f) && (z2 > 0.f) && (fabsf(area) > 1e-9f);
    float invA = __fdiv_rn(1.0f, area);

    float xmn = fminf(x0, fminf(x1, x2));
    float xmx = fmaxf(x0, fmaxf(x1, x2));
    float ymn = fminf(y0, fminf(y1, y2));
    float ymx = fmaxf(y0, fmaxf(y1, y2));
    int fxmn = (int)floorf(xmn);
    int fymn = (int)floorf(ymn);
    int bcx = min(max(fxmn, 0), W_ - KK);
    int bcy = min(max(fymn, 0), H_ - KK);

    int xlo = max(bcx, fxmn);
    int xhi = min(bcx + KK - 1, (int)ceilf(xmx));
    int ylo = max(bcy, fymn);
    int yhi = min(bcy + KK - 1, (int)ceilf(ymx));
    int bw = xhi - xlo + 1;
    int bh = yhi - ylo + 1;
    int cnt = (ok && bw > 0 && bh > 0) ? bw * bh : 0;
    // Exact division t/bw for t < 2^16 via magic multiply.
    unsigned magic = (65536u + (unsigned)bw - 1) / (unsigned)max(bw, 1);

    unsigned long long* zb = g_zbuf + (size_t)n * HW;

    for (int t = sub; t < cnt; t += 16) {
        int oy = (int)(((unsigned)t * magic) >> 16);
        int ox = t - oy * bw;
        int px = xlo + ox;
        int py = ylo + oy;
        float pxf = (float)px, pyf = (float)py;
        float w0 = __fmul_rn(edgefn(x2, x1, pyf, y1, y2, y1, pxf, x1), invA);
        float w1 = __fmul_rn(edgefn(x0, x2, pyf, y2, y0, y2, pxf, x2), invA);
        float w2 = __fsub_rn(__fsub_rn(1.0f, w0), w1);
        if (w0 >= 0.f && w1 >= 0.f && w2 >= 0.f) {
            float depth = __fadd_rn(
                __fadd_rn(__fmul_rn(w0, z0), __fmul_rn(w1, z1)),
                __fmul_rn(w2, z2));
            // Same-pixel ties only arise between DIFFERENT triangles, so
            // packing f preserves the reference's (depth, m) tie-break.
            unsigned long long packed =
                ((unsigned long long)__float_as_uint(depth) << 32) |
                (unsigned int)f;
            atomicMin(zb + py * W_ + px, packed);
        }
    }
}

// Per-pixel shading body: identical arithmetic to the proven R12 version.
__device__ __forceinline__ void shade_pixel(unsigned long long zv, int n,
                                            int pix, const float* vals,
                                            float& ou, float& ov, float& om) {
    float u = 0.f, v = 0.f;
    if (zv != 0xFFFFFFFFFFFFFFFFull) {
        int f = (int)(unsigned int)(zv & 0xFFFFFFFFu);
        int4 fc = g_faces4[f];
        const float4* pv = g_pv + n * NV;
        float4 p0 = pv[fc.x];
        float4 p1 = pv[fc.y];
        float4 p2 = pv[fc.z];
        float x0 = p0.x, y0 = p0.y;
        float x1 = p1.x, y1 = p1.y;
        float x2 = p2.x, y2 = p2.y;
        float area = edgefn(x1, x0, y2, y0, y1, y0, x2, x0);
        float invA = __fdiv_rn(1.0f, area);
        int px = pix & (W_ - 1);
        int py = pix >> 9;
        float pxf = (float)px, pyf = (float)py;
        float w0 = __fmul_rn(edgefn(x2, x1, pyf, y1, y2, y1, pxf, x1), invA);
        float w1 = __fmul_rn(edgefn(x0, x2, pyf, y2, y0, y2, pxf, x2), invA);
        float w2 = __fsub_rn(__fsub_rn(1.0f, w0), w1);
        const float2* vl = reinterpret_cast<const float2*>(vals);
        float2 va = vl[fc.x];
        float2 vbv = vl[fc.y];
        float2 vc = vl[fc.z];
        u = __fadd_rn(
            __fadd_rn(__fmul_rn(w0, va.x), __fmul_rn(w1, vbv.x)),
            __fmul_rn(w2, vc.x));
        v = __fadd_rn(
            __fadd_rn(__fmul_rn(w0, va.y), __fmul_rn(w1, vbv.y)),
            __fmul_rn(w2, vc.y));
    }
    float mask = (u > 0.f || v > 0.f) ? 1.f : 0.f;
    if (mask > 0.f) {
        ou = __fsub_rn(__fmul_rn(2.f, u), 1.f);
        ov = __fsub_rn(__fmul_rn(2.f, v), 1.f);
    } else {
        ou = -10.f;
        ov = -10.f;
    }
    om = mask;
}

// TWO adjacent pixels per thread: one 16B zbuf load, three 8B output stores.
__global__ void shade_kernel(const float* __restrict__ vals,
                             float* __restrict__ out) {
    int gid = blockIdx.x * blockDim.x + threadIdx.x;
    if (gid >= (NB * HW) / 2) return;
    int n = gid / (HW / 2);
    int pix = (gid - n * (HW / 2)) * 2;

    ulonglong2 zv2 = reinterpret_cast<const ulonglong2*>(
        g_zbuf + (size_t)n * HW + pix)[0];

    float ou0, ov0, om0, ou1, ov1, om1;
    shade_pixel(zv2.x, n, pix + 0, vals, ou0, ov0, om0);
    shade_pixel(zv2.y, n, pix + 1, vals, ou1, ov1, om1);

    float2* uplane = reinterpret_cast<float2*>(out + ((size_t)n * 2 + 0) * HW + pix);
    float2* vplane = reinterpret_cast<float2*>(out + ((size_t)n * 2 + 1) * HW + pix);
    float2* mplane = reinterpret_cast<float2*>(out + (size_t)NB * 2 * HW + (size_t)n * HW + pix);
    uplane[0] = make_float2(ou0, ou1);
    vplane[0] = make_float2(ov0, ov1);
    mplane[0] = make_float2(om0, om1);
}

extern "C" void kernel_launch(void* const* d_in, const int* in_sizes, int n_in,
                              void* d_out, int out_size) {
    const float* verts = (const float*)d_in[0];
    const int* faces = (const int*)d_in[1];
    const float* vals = (const float*)d_in[2];
    float* out = (float*)d_out;

    (void)in_sizes; (void)n_in; (void)out_size;

    int prepBlocks = ((NB * HW) / 2 + 255) / 256;   // covers fill, proj, faces
    prep_kernel<<<prepBlocks, 256>>>(verts, faces);

    int nwarps = NTRI / 2;                 // 53792 warps, 2 tri each
    int rasterBlocks = (nwarps * 32 + 255) / 256;
    raster_kernel<<<rasterBlocks, 256>>>();

    int shadeBlocks = ((NB * HW) / 2 + 255) / 256;
    shade_kernel<<<shadeBlocks, 256>>>(vals, out);
}